// round 4
// baseline (speedup 1.0000x reference)
#include <cuda_runtime.h>
#include <cstdint>

// Problem constants
#define T_DIM 1024
#define B_DIM 4
#define S_DIM 1024
#define E_DIM 1024
#define H_DIM 16
#define D_DIM 64
#define TB (T_DIM * B_DIM)
#define BE (B_DIM * E_DIM)   // 4096: row stride of [T,B,E] / [S,B,E]

// Scratch (device globals — no allocation allowed)
__device__ float g_Q[TB * E_DIM];
__device__ float g_K[TB * E_DIM];
__device__ float g_V[TB * E_DIM];
__device__ float g_Ctx[TB * E_DIM];

// ---------------------------------------------------------------------------
// tf32 helpers
// ---------------------------------------------------------------------------
__device__ __forceinline__ uint32_t f2tf(float x) {
    uint32_t r;
    asm("cvt.rna.tf32.f32 %0, %1;" : "=r"(r) : "f"(x));
    return r;
}

__device__ __forceinline__ void mma8(float* d, const uint32_t* a, const uint32_t* b) {
    asm volatile(
        "mma.sync.aligned.m16n8k8.row.col.f32.tf32.tf32.f32 "
        "{%0,%1,%2,%3}, {%4,%5,%6,%7}, {%8,%9}, {%0,%1,%2,%3};\n"
        : "+f"(d[0]), "+f"(d[1]), "+f"(d[2]), "+f"(d[3])
        : "r"(a[0]), "r"(a[1]), "r"(a[2]), "r"(a[3]), "r"(b[0]), "r"(b[1]));
}

#define PBK 32
#define LDA 132

// ---------------------------------------------------------------------------
// Projection / output GEMM: C = alpha*(A[M,1024] @ W[1024,1024]^T + bias)
// 128x128x32 tile, 8 warps (2m x 4n), m16n8k8 tf32 (unchanged from R3)
// ---------------------------------------------------------------------------
__global__ void __launch_bounds__(256) gemm_tf32_bias(
    const float* __restrict__ A, const float* __restrict__ W,
    const float* __restrict__ bias, float* __restrict__ C, float alpha)
{
    __shared__ uint32_t As[PBK][LDA];
    __shared__ uint32_t Bs[PBK][LDA];
    const int tid = threadIdx.x, lane = tid & 31, wid = tid >> 5;
    const int wm = (wid >> 2) * 64, wn = (wid & 3) * 32;
    const int m0 = blockIdx.y * 128, n0 = blockIdx.x * 128;
    const int g = lane >> 2, tg = lane & 3;

    float acc[4][4][4];
    #pragma unroll
    for (int i = 0; i < 4; i++)
        #pragma unroll
        for (int j = 0; j < 4; j++)
            #pragma unroll
            for (int q = 0; q < 4; q++) acc[i][j][q] = 0.f;

    const int lrow = tid >> 3, lkc = (tid & 7) << 2;
    float4 pa[4], pw[4];
    #pragma unroll
    for (int p = 0; p < 4; p++) {
        int row = lrow + p * 32;
        pa[p] = *(const float4*)(A + (long)(m0 + row) * E_DIM + lkc);
        pw[p] = *(const float4*)(W + (long)(n0 + row) * E_DIM + lkc);
    }

    for (int k0 = 0; k0 < E_DIM; k0 += PBK) {
        #pragma unroll
        for (int p = 0; p < 4; p++) {
            int row = lrow + p * 32;
            As[lkc + 0][row] = f2tf(pa[p].x); As[lkc + 1][row] = f2tf(pa[p].y);
            As[lkc + 2][row] = f2tf(pa[p].z); As[lkc + 3][row] = f2tf(pa[p].w);
            Bs[lkc + 0][row] = f2tf(pw[p].x); Bs[lkc + 1][row] = f2tf(pw[p].y);
            Bs[lkc + 2][row] = f2tf(pw[p].z); Bs[lkc + 3][row] = f2tf(pw[p].w);
        }
        __syncthreads();

        if (k0 + PBK < E_DIM) {
            #pragma unroll
            for (int p = 0; p < 4; p++) {
                int row = lrow + p * 32;
                pa[p] = *(const float4*)(A + (long)(m0 + row) * E_DIM + k0 + PBK + lkc);
                pw[p] = *(const float4*)(W + (long)(n0 + row) * E_DIM + k0 + PBK + lkc);
            }
        }

        #pragma unroll
        for (int ks = 0; ks < PBK; ks += 8) {
            uint32_t af[4][4], bf[4][2];
            #pragma unroll
            for (int mt = 0; mt < 4; mt++) {
                int r = wm + mt * 16 + g;
                af[mt][0] = As[ks + tg][r];
                af[mt][1] = As[ks + tg][r + 8];
                af[mt][2] = As[ks + tg + 4][r];
                af[mt][3] = As[ks + tg + 4][r + 8];
            }
            #pragma unroll
            for (int nt = 0; nt < 4; nt++) {
                int n = wn + nt * 8 + g;
                bf[nt][0] = Bs[ks + tg][n];
                bf[nt][1] = Bs[ks + tg + 4][n];
            }
            #pragma unroll
            for (int mt = 0; mt < 4; mt++)
                #pragma unroll
                for (int nt = 0; nt < 4; nt++)
                    mma8(acc[mt][nt], af[mt], bf[nt]);
        }
        __syncthreads();
    }

    #pragma unroll
    for (int mt = 0; mt < 4; mt++) {
        int r0 = m0 + wm + mt * 16 + g;
        #pragma unroll
        for (int nt = 0; nt < 4; nt++) {
            int c = n0 + wn + nt * 8 + 2 * tg;
            float2 bv = *(const float2*)(bias + c);
            float2 o0, o1;
            o0.x = alpha * (acc[mt][nt][0] + bv.x);
            o0.y = alpha * (acc[mt][nt][1] + bv.y);
            o1.x = alpha * (acc[mt][nt][2] + bv.x);
            o1.y = alpha * (acc[mt][nt][3] + bv.y);
            *(float2*)(C + (long)r0 * E_DIM + c) = o0;
            *(float2*)(C + (long)(r0 + 8) * E_DIM + c) = o1;
        }
    }
}

// ---------------------------------------------------------------------------
// Fused attention: block = (16 T-rows, batch b); loops all 16 heads.
// Per head: QK^T (tf32 MMA) -> smem scores -> softmax (+masks) ->
//   avg accumulate in regs -> tf32 p in smem -> PV MMA -> ctx write.
// At end: writes avgw = sum_h p / 16. P never touches DRAM.
//
// SMEM (words): Qs[64][20]=1280 | BV=8704 (K:[64][132] / V:[128][68]) |
//               Sc[16][1032]=16512  -> total 26496 w = 105984 B
// ---------------------------------------------------------------------------
#define QS_OFF 0
#define BV_OFF 1280
#define SC_OFF (1280 + 8704)
#define FA_SMEM_BYTES ((1280 + 8704 + 16512) * 4)

__global__ void __launch_bounds__(256) fused_attn(
    const float* __restrict__ Q, const float* __restrict__ Kx,
    const float* __restrict__ V, const float* __restrict__ amask,
    const int* __restrict__ pad, float* __restrict__ Ctx,
    float* __restrict__ avgw)
{
    extern __shared__ uint32_t sw[];
    uint32_t* Qs = sw + QS_OFF;          // [64 k][20] (16 rows + pad)
    uint32_t* BV = sw + BV_OFF;          // K chunk [64][132] or V chunk [128][68]
    float*    Sc = (float*)(sw + SC_OFF);// [16][1032]

    const int tid = threadIdx.x, lane = tid & 31, wid = tid >> 5;
    const int g = lane >> 2, tg = lane & 3;
    const int t0 = blockIdx.x * 16;
    const int b  = blockIdx.y;

    float4 ravg[2][8];
    #pragma unroll
    for (int i = 0; i < 2; i++)
        #pragma unroll
        for (int j = 0; j < 8; j++) ravg[i][j] = make_float4(0.f, 0.f, 0.f, 0.f);

    const int stg_s  = tid >> 4;           // 0..15 (+p*16)
    const int stg_d4 = (tid & 15) << 2;    // 0..60

    for (int h = 0; h < H_DIM; h++) {
        const float* Qb = Q  + (long)b * E_DIM + h * D_DIM;
        const float* Kb = Kx + (long)b * E_DIM + h * D_DIM;
        const float* Vb = V  + (long)b * E_DIM + h * D_DIM;

        // ---- Q tile: 16 x 64 -> Qs[d][r] (safe: Qs last read pre-softmax-sync)
        {
            int r = tid >> 4, d4 = (tid & 15) << 2;
            float4 q4 = *(const float4*)(Qb + (long)(t0 + r) * BE + d4);
            Qs[(d4 + 0) * 20 + r] = f2tf(q4.x);
            Qs[(d4 + 1) * 20 + r] = f2tf(q4.y);
            Qs[(d4 + 2) * 20 + r] = f2tf(q4.z);
            Qs[(d4 + 3) * 20 + r] = f2tf(q4.w);
        }

        // ---- score phase: Sc[16][1024] = Q @ K^T (raw) ----
        const int wn = wid * 16;
        float4 kst[8];
        #pragma unroll
        for (int p = 0; p < 8; p++)
            kst[p] = *(const float4*)(Kb + (long)(stg_s + p * 16) * BE + stg_d4);

        for (int c = 0; c < 8; c++) {
            __syncthreads();   // BV free of prev-chunk readers; Qs visible (c=0)
            #pragma unroll
            for (int p = 0; p < 8; p++) {
                int s = stg_s + p * 16;
                BV[(stg_d4 + 0) * 132 + s] = f2tf(kst[p].x);
                BV[(stg_d4 + 1) * 132 + s] = f2tf(kst[p].y);
                BV[(stg_d4 + 2) * 132 + s] = f2tf(kst[p].z);
                BV[(stg_d4 + 3) * 132 + s] = f2tf(kst[p].w);
            }
            if (c < 7) {
                #pragma unroll
                for (int p = 0; p < 8; p++)
                    kst[p] = *(const float4*)(Kb + (long)((c + 1) * 128 + stg_s + p * 16) * BE + stg_d4);
            }
            __syncthreads();

            float acc[2][4] = {{0.f,0.f,0.f,0.f},{0.f,0.f,0.f,0.f}};
            #pragma unroll
            for (int ks = 0; ks < 64; ks += 8) {
                uint32_t af[4], bf[2][2];
                af[0] = Qs[(ks + tg) * 20 + g];
                af[1] = Qs[(ks + tg) * 20 + g + 8];
                af[2] = Qs[(ks + tg + 4) * 20 + g];
                af[3] = Qs[(ks + tg + 4) * 20 + g + 8];
                #pragma unroll
                for (int nt = 0; nt < 2; nt++) {
                    int n = wn + nt * 8 + g;
                    bf[nt][0] = BV[(ks + tg) * 132 + n];
                    bf[nt][1] = BV[(ks + tg + 4) * 132 + n];
                }
                mma8(acc[0], af, bf[0]);
                mma8(acc[1], af, bf[1]);
            }
            int cbase = c * 128 + wn;
            #pragma unroll
            for (int nt = 0; nt < 2; nt++) {
                int cc = cbase + nt * 8 + 2 * tg;
                *(float2*)&Sc[g * 1032 + cc]       = make_float2(acc[nt][0], acc[nt][1]);
                *(float2*)&Sc[(g + 8) * 1032 + cc] = make_float2(acc[nt][2], acc[nt][3]);
            }
        }
        __syncthreads();

        // ---- softmax (warp owns rows wid*2, wid*2+1) + avg accumulate ----
        #pragma unroll
        for (int i = 0; i < 2; i++) {
            int r = wid * 2 + i;
            int t = t0 + r;
            const float4* am = (const float4*)(amask + (long)t * S_DIM);
            const int4*  pd  = (const int4*)(pad + b * S_DIM);
            float4* scr = (float4*)(Sc + r * 1032);
            float4 v[8];
            float mx = -3.0e38f;
            #pragma unroll
            for (int jj = 0; jj < 8; jj++) {
                int cc = lane + 32 * jj;
                float4 sv = scr[cc];
                float4 av = am[cc];
                int4 p4 = pd[cc];
                sv.x += av.x + (p4.x ? -1e30f : 0.f);
                sv.y += av.y + (p4.y ? -1e30f : 0.f);
                sv.z += av.z + (p4.z ? -1e30f : 0.f);
                sv.w += av.w + (p4.w ? -1e30f : 0.f);
                v[jj] = sv;
                mx = fmaxf(mx, fmaxf(fmaxf(sv.x, sv.y), fmaxf(sv.z, sv.w)));
            }
            #pragma unroll
            for (int o = 16; o; o >>= 1) mx = fmaxf(mx, __shfl_xor_sync(0xffffffffu, mx, o));
            float sum = 0.f;
            #pragma unroll
            for (int jj = 0; jj < 8; jj++) {
                v[jj].x = __expf(v[jj].x - mx); v[jj].y = __expf(v[jj].y - mx);
                v[jj].z = __expf(v[jj].z - mx); v[jj].w = __expf(v[jj].w - mx);
                sum += v[jj].x + v[jj].y + v[jj].z + v[jj].w;
            }
            #pragma unroll
            for (int o = 16; o; o >>= 1) sum += __shfl_xor_sync(0xffffffffu, sum, o);
            float inv = 1.0f / sum;
            uint4* scu = (uint4*)(Sc + r * 1032);
            #pragma unroll
            for (int jj = 0; jj < 8; jj++) {
                float4 pv;
                pv.x = v[jj].x * inv; pv.y = v[jj].y * inv;
                pv.z = v[jj].z * inv; pv.w = v[jj].w * inv;
                ravg[i][jj].x += pv.x; ravg[i][jj].y += pv.y;
                ravg[i][jj].z += pv.z; ravg[i][jj].w += pv.w;
                uint4 u;
                u.x = f2tf(pv.x); u.y = f2tf(pv.y);
                u.z = f2tf(pv.z); u.w = f2tf(pv.w);
                scu[lane + 32 * jj] = u;
            }
        }

        // ---- PV phase: ctx[16 x 64] = P @ V (warp owns 8 d-cols) ----
        const int pwn = wid * 8;
        float pacc[4] = {0.f, 0.f, 0.f, 0.f};
        #pragma unroll
        for (int p = 0; p < 8; p++)
            kst[p] = *(const float4*)(Vb + (long)(stg_s + p * 16) * BE + stg_d4);

        for (int c = 0; c < 8; c++) {
            __syncthreads();   // covers softmax Sc writes (c=0) & prev-chunk BV reads
            #pragma unroll
            for (int p = 0; p < 8; p++) {
                int s = stg_s + p * 16;
                BV[s * 68 + stg_d4 + 0] = f2tf(kst[p].x);
                BV[s * 68 + stg_d4 + 1] = f2tf(kst[p].y);
                BV[s * 68 + stg_d4 + 2] = f2tf(kst[p].z);
                BV[s * 68 + stg_d4 + 3] = f2tf(kst[p].w);
            }
            if (c < 7) {
                #pragma unroll
                for (int p = 0; p < 8; p++)
                    kst[p] = *(const float4*)(Vb + (long)((c + 1) * 128 + stg_s + p * 16) * BE + stg_d4);
            }
            __syncthreads();

            const uint32_t* scu = (const uint32_t*)Sc;
            #pragma unroll
            for (int ks = 0; ks < 128; ks += 8) {
                uint32_t af[4], bf[2];
                int col = c * 128 + ks;
                af[0] = scu[g * 1032 + col + tg];
                af[1] = scu[(g + 8) * 1032 + col + tg];
                af[2] = scu[g * 1032 + col + tg + 4];
                af[3] = scu[(g + 8) * 1032 + col + tg + 4];
                bf[0] = BV[(ks + tg) * 68 + pwn + g];
                bf[1] = BV[(ks + tg + 4) * 68 + pwn + g];
                mma8(pacc, af, bf);
            }
        }
        {
            int d = pwn + 2 * tg;
            *(float2*)(Ctx + (long)(t0 + g) * BE + b * E_DIM + h * D_DIM + d) =
                make_float2(pacc[0], pacc[1]);
            *(float2*)(Ctx + (long)(t0 + g + 8) * BE + b * E_DIM + h * D_DIM + d) =
                make_float2(pacc[2], pacc[3]);
        }
    }

    // ---- write avg_weights = (1/16) * sum_h p ----
    const float inv16 = 1.0f / 16.0f;
    #pragma unroll
    for (int i = 0; i < 2; i++) {
        int t = t0 + wid * 2 + i;
        float4* ap = (float4*)(avgw + ((long)b * T_DIM + t) * S_DIM);
        #pragma unroll
        for (int jj = 0; jj < 8; jj++) {
            float4 o = ravg[i][jj];
            o.x *= inv16; o.y *= inv16; o.z *= inv16; o.w *= inv16;
            ap[lane + 32 * jj] = o;
        }
    }
}

// ---------------------------------------------------------------------------
extern "C" void kernel_launch(void* const* d_in, const int* in_sizes, int n_in,
                              void* d_out, int out_size) {
    const float* query = (const float*)d_in[0];
    const float* key   = (const float*)d_in[1];
    const float* value = (const float*)d_in[2];
    const int*   pad   = (const int*)d_in[3];
    const float* amask = (const float*)d_in[4];
    const float* ipw   = (const float*)d_in[5];
    const float* ipb   = (const float*)d_in[6];
    const float* ow    = (const float*)d_in[7];
    const float* ob    = (const float*)d_in[8];

    float* out  = (float*)d_out;
    float* avgw = out + (long)T_DIM * B_DIM * E_DIM;

    float *Qp, *Kp, *Vp, *Cp;
    cudaGetSymbolAddress((void**)&Qp, g_Q);
    cudaGetSymbolAddress((void**)&Kp, g_K);
    cudaGetSymbolAddress((void**)&Vp, g_V);
    cudaGetSymbolAddress((void**)&Cp, g_Ctx);

    cudaFuncSetAttribute(fused_attn,
                         cudaFuncAttributeMaxDynamicSharedMemorySize,
                         FA_SMEM_BYTES);

    dim3 gproj(E_DIM / 128, TB / 128);   // (8, 32)
    gemm_tf32_bias<<<gproj, 256>>>(query, ipw,                     ipb,             Qp, 0.125f);
    gemm_tf32_bias<<<gproj, 256>>>(key,   ipw + E_DIM * E_DIM,     ipb + E_DIM,     Kp, 1.0f);
    gemm_tf32_bias<<<gproj, 256>>>(value, ipw + 2 * E_DIM * E_DIM, ipb + 2 * E_DIM, Vp, 1.0f);

    fused_attn<<<dim3(T_DIM / 16, B_DIM), 256, FA_SMEM_BYTES>>>(
        Qp, Kp, Vp, amask, pad, Cp, avgw);

    gemm_tf32_bias<<<gproj, 256>>>(Cp, ow, ob, out, 1.0f);
}